// round 2
// baseline (speedup 1.0000x reference)
#include <cuda_runtime.h>
#include <cuda_bf16.h>

#define MAXB 64
#define THREADS 256
#define CAP (1 << 23)   // max points for compact zseg path (33.5 MB static)

// ---------------- device scratch (no allocations allowed) ----------------
__device__ unsigned g_gmax[MAXB];
__device__ unsigned g_pmin[MAXB];
__device__ unsigned g_zmin[MAXB];
__device__ unsigned g_zmax[MAXB];
__device__ int      g_hasg[MAXB];
__device__ int      g_hasp[MAXB];
__device__ double   g_sum;
__device__ float    g_zseg[CAP];    // z with segment packed in mantissa LSB

// order-preserving float <-> uint
__device__ __forceinline__ unsigned ordf(float f) {
    unsigned u = __float_as_uint(f);
    return (u & 0x80000000u) ? ~u : (u | 0x80000000u);
}
__device__ __forceinline__ float deordf(unsigned o) {
    unsigned u = (o & 0x80000000u) ? (o & 0x7FFFFFFFu) : ~o;
    return __uint_as_float(u);
}
__device__ __forceinline__ float frcp(float x) {
    float r; asm("rcp.approx.f32 %0, %1;" : "=f"(r) : "f"(x)); return r;
}
__device__ __forceinline__ float packzs(float z, int s) {
    return __uint_as_float((__float_as_uint(z) & ~1u) | (unsigned)(s & 1));
}

// ---------------- kernel 0: reset (graph replays) ----------------
__global__ void k_init(int B) {
    int t = blockIdx.x * blockDim.x + threadIdx.x;
    if (t < B) {
        g_gmax[t] = 0u;        g_pmin[t] = 0xFFFFFFFFu;
        g_zmin[t] = 0xFFFFFFFFu; g_zmax[t] = 0u;
        g_hasg[t] = 0;         g_hasp[t] = 0;
    }
    if (t == 0) g_sum = 0.0;
}

// ---------------- kernel 1: per-cloud z reductions + compact zseg ----------------
__global__ void __launch_bounds__(THREADS) k_pass1(
    const float4* __restrict__ coord4, const int4* __restrict__ seg4,
    const float*  __restrict__ coord,  const int*  __restrict__ segment,
    const int* __restrict__ offset, int n, int B, int gpb, int writeZ)
{
    __shared__ unsigned s_gmax[MAXB], s_pmin[MAXB], s_zmin[MAXB], s_zmax[MAXB];
    __shared__ int s_hasg[MAXB], s_hasp[MAXB], s_off[MAXB];

    int t = threadIdx.x;
    for (int j = t; j < B; j += THREADS) {
        s_gmax[j] = 0u; s_pmin[j] = 0xFFFFFFFFu;
        s_zmin[j] = 0xFFFFFFFFu; s_zmax[j] = 0u;
        s_hasg[j] = 0; s_hasp[j] = 0;
        s_off[j]  = offset[j];
    }
    __syncthreads();

    int curb = 0;                          // monotone batch cursor
    unsigned lg = 0u, lp = 0xFFFFFFFFu, lzm = 0xFFFFFFFFu, lzx = 0u;
    int hg = 0, hp = 0;

    auto flush = [&]() {
        atomicMin(&s_zmin[curb], lzm);
        atomicMax(&s_zmax[curb], lzx);
        if (hg) { atomicMax(&s_gmax[curb], lg); s_hasg[curb] = 1; }
        if (hp) { atomicMin(&s_pmin[curb], lp); s_hasp[curb] = 1; }
        lg = 0u; lp = 0xFFFFFFFFu; lzm = 0xFFFFFFFFu; lzx = 0u;
        hg = 0; hp = 0;
    };
    auto upd = [&](int i, float z, int s) {
        while (i >= s_off[curb]) { flush(); curb++; }   // ~0 iters/point
        unsigned o = ordf(z);
        lzm = min(lzm, o);
        lzx = max(lzx, o);
        if (s == 0) { lg = max(lg, o); hg = 1; }
        else        { lp = min(lp, o); hp = 1; }
    };

    int n4 = n >> 2;
    int g0 = blockIdx.x * gpb;
    int g1 = min(g0 + gpb, n4);
    for (int g = g0 + t; g < g1; g += THREADS) {
        float4 a = coord4[3 * g + 0];
        float4 b = coord4[3 * g + 1];
        float4 c = coord4[3 * g + 2];
        int4   s = seg4[g];
        int i0 = g << 2;
        upd(i0 + 0, a.z, s.x);
        upd(i0 + 1, b.y, s.y);
        upd(i0 + 2, c.x, s.z);
        upd(i0 + 3, c.w, s.w);
        if (writeZ) {
            float4 zs;
            zs.x = packzs(a.z, s.x);
            zs.y = packzs(b.y, s.y);
            zs.z = packzs(c.x, s.z);
            zs.w = packzs(c.w, s.w);
            *reinterpret_cast<float4*>(g_zseg + i0) = zs;
        }
    }
    // scalar tail (block 0 only)
    int tail0 = n4 << 2;
    if (blockIdx.x == 0 && t < (n - tail0)) {
        int i = tail0 + t;
        float z = coord[3 * i + 2];
        int   s = segment[i];
        upd(i, z, s);
        if (writeZ) g_zseg[i] = packzs(z, s);
    }
    flush();   // identity values no-op for threads that saw nothing

    __syncthreads();
    for (int j = t; j < B; j += THREADS) {
        atomicMin(&g_zmin[j], s_zmin[j]);
        atomicMax(&g_zmax[j], s_zmax[j]);
        if (s_hasg[j]) { atomicMax(&g_gmax[j], s_gmax[j]); g_hasg[j] = 1; }
        if (s_hasp[j]) { atomicMin(&g_pmin[j], s_pmin[j]); g_hasp[j] = 1; }
    }
}

// ---------------- kernel 2: focal-CE * gaussian weight, reduce ----------------
// term = softplus(v) * sigmoid(v)^2 * w,  v = logit_other - logit_target
__device__ __forceinline__ float pointTerm(float p0, float p1, int s, float z, float mu)
{
    float tgt = s ? p1 : p0;
    float oth = s ? p0 : p1;
    float v  = oth - tgt;
    float e  = __expf(-fabsf(v));
    float inv = frcp(1.0f + e);
    float sig = (v >= 0.0f ? 1.0f : e) * inv;          // sigmoid(v) = 1 - p_t
    float sp  = fmaxf(v, 0.0f) + __logf(1.0f + e);     // softplus(v) = -log p_t
    float d  = z - mu;
    float dd = d * d;
    float cf = (d <= 0.0f) ? -50.0f : -3.125f;         // 1/(2*0.1^2), 1/(2*0.4^2)
    float w  = __expf(cf * dd);
    if (d > 0.8f) w = 0.1f;                            // clamp, 2*SIGMA_R
    return sp * sig * sig * w;
}

template <bool USEZ>
__global__ void __launch_bounds__(THREADS) k_loss(
    const float4* __restrict__ pred4, const float* __restrict__ pred,
    const float4* __restrict__ coord4, const float* __restrict__ coord,
    const int4* __restrict__ seg4, const int* __restrict__ segment,
    const int* __restrict__ offset, int n, int B, int gpb)
{
    __shared__ int   s_off[MAXB];
    __shared__ float s_mu[MAXB];
    __shared__ float s_part[THREADS / 32];

    int t = threadIdx.x;
    for (int j = t; j < B; j += THREADS) {
        s_off[j] = offset[j];
        float g = g_hasg[j] ? deordf(g_gmax[j]) : deordf(g_zmin[j]);
        float p = g_hasp[j] ? deordf(g_pmin[j]) : deordf(g_zmax[j]);
        s_mu[j] = g + (p - g) * 0.5f;
    }
    __syncthreads();

    float acc = 0.0f;
    int curb = 0;

    int n4 = n >> 2;
    int g0 = blockIdx.x * gpb;
    int g1 = min(g0 + gpb, n4);
    for (int g = g0 + t; g < g1; g += THREADS) {
        float4 pa = pred4[2 * g + 0];
        float4 pb = pred4[2 * g + 1];
        int i0 = g << 2;

        float z0, z1, z2, z3;
        int s0, s1, s2, s3;
        if (USEZ) {
            float4 zs = *reinterpret_cast<const float4*>(g_zseg + i0);
            z0 = zs.x; z1 = zs.y; z2 = zs.z; z3 = zs.w;
            s0 = __float_as_uint(zs.x) & 1;
            s1 = __float_as_uint(zs.y) & 1;
            s2 = __float_as_uint(zs.z) & 1;
            s3 = __float_as_uint(zs.w) & 1;
        } else {
            float4 a = coord4[3 * g + 0];
            float4 b = coord4[3 * g + 1];
            float4 c = coord4[3 * g + 2];
            int4   s = seg4[g];
            z0 = a.z; z1 = b.y; z2 = c.x; z3 = c.w;
            s0 = s.x; s1 = s.y; s2 = s.z; s3 = s.w;
        }

        while (i0 >= s_off[curb]) curb++;   // monotone, ~0 iters
        float mu0, mu1, mu2, mu3;
        if (i0 + 3 < s_off[curb]) {         // fast path: whole group same batch
            mu0 = mu1 = mu2 = mu3 = s_mu[curb];
        } else {                            // rare straddle
            int b1 = curb; while (i0 + 1 >= s_off[b1]) b1++;
            int b2 = b1;   while (i0 + 2 >= s_off[b2]) b2++;
            int b3 = b2;   while (i0 + 3 >= s_off[b3]) b3++;
            mu0 = s_mu[curb]; mu1 = s_mu[b1]; mu2 = s_mu[b2]; mu3 = s_mu[b3];
            curb = b3;
        }

        acc += pointTerm(pa.x, pa.y, s0, z0, mu0);
        acc += pointTerm(pa.z, pa.w, s1, z1, mu1);
        acc += pointTerm(pb.x, pb.y, s2, z2, mu2);
        acc += pointTerm(pb.z, pb.w, s3, z3, mu3);
    }

    // scalar tail (block 0)
    int tail0 = n4 << 2;
    if (blockIdx.x == 0 && t < (n - tail0)) {
        int i = tail0 + t;
        int b = 0; while (i >= s_off[b]) b++;
        float p0 = pred[2 * i], p1 = pred[2 * i + 1];
        float z; int s;
        if (USEZ) {
            float zz = g_zseg[i];
            s = __float_as_uint(zz) & 1; z = zz;
        } else {
            z = coord[3 * i + 2]; s = segment[i];
        }
        acc += pointTerm(p0, p1, s, z, s_mu[b]);
    }

    // reduce: warp shuffle -> shared -> warp 0 -> one double atomic
    #pragma unroll
    for (int o = 16; o > 0; o >>= 1) acc += __shfl_xor_sync(0xFFFFFFFFu, acc, o);
    int warp = t >> 5, lane = t & 31;
    if (lane == 0) s_part[warp] = acc;
    __syncthreads();
    if (warp == 0) {
        float v = (lane < (THREADS / 32)) ? s_part[lane] : 0.0f;
        #pragma unroll
        for (int o = 16; o > 0; o >>= 1) v += __shfl_xor_sync(0xFFFFFFFFu, v, o);
        if (lane == 0) atomicAdd(&g_sum, (double)v);
    }
}

// ---------------- kernel 3: finalize ----------------
__global__ void k_fin(float* out, int n) {
    out[0] = (float)(g_sum / (double)n);
}

// ---------------- launch ----------------
extern "C" void kernel_launch(void* const* d_in, const int* in_sizes, int n_in,
                              void* d_out, int out_size)
{
    const float* pred    = (const float*)d_in[0];
    const float* coord   = (const float*)d_in[1];
    const int*   segment = (const int*)d_in[2];
    const int*   offset  = (const int*)d_in[3];
    int n = in_sizes[2];
    int B = in_sizes[3];
    if (B > MAXB) B = MAXB;

    int n4 = n >> 2;
    int blocks = 148 * 8;
    int gpb = (n4 + blocks - 1) / blocks;
    if (gpb < 1) gpb = 1;
    int useZ = (n <= CAP) ? 1 : 0;

    k_init<<<1, MAXB>>>(B);
    k_pass1<<<blocks, THREADS>>>((const float4*)coord, (const int4*)segment,
                                 coord, segment, offset, n, B, gpb, useZ);
    if (useZ) {
        k_loss<true><<<blocks, THREADS>>>((const float4*)pred, pred,
                                          (const float4*)coord, coord,
                                          (const int4*)segment, segment,
                                          offset, n, B, gpb);
    } else {
        k_loss<false><<<blocks, THREADS>>>((const float4*)pred, pred,
                                           (const float4*)coord, coord,
                                           (const int4*)segment, segment,
                                           offset, n, B, gpb);
    }
    k_fin<<<1, 1>>>((float*)d_out, n);
}

// round 3
// speedup vs baseline: 1.2257x; 1.2257x over previous
#include <cuda_runtime.h>
#include <cuda_bf16.h>

#define THREADS 256
#define MAXB    64
#define MAXBLK  8192

// ---------------- device scratch (zero-initialized at load; no allocs) ----------------
__device__ unsigned d_gmax[MAXBLK * MAXB];   // per-block-per-batch partials (ord-encoded)
__device__ unsigned d_pmin[MAXBLK * MAXB];
__device__ unsigned d_zmin[MAXBLK * MAXB];
__device__ unsigned d_zmax[MAXBLK * MAXB];
__device__ float    d_part[MAXBLK];          // per-block loss partials
__device__ float    d_mu[MAXB];
__device__ unsigned d_count;                 // completion counter (reset by k_mid)

// order-preserving float <-> uint (normal floats never map to 0u or ~0u)
__device__ __forceinline__ unsigned ordf(float f) {
    unsigned u = __float_as_uint(f);
    return (u & 0x80000000u) ? ~u : (u | 0x80000000u);
}
__device__ __forceinline__ float deordf(unsigned o) {
    unsigned u = (o & 0x80000000u) ? (o & 0x7FFFFFFFu) : ~o;
    return __uint_as_float(u);
}
__device__ __forceinline__ float frcp(float x) {
    float r; asm("rcp.approx.f32 %0, %1;" : "=f"(r) : "f"(x)); return r;
}

// ---------------- kernel 1: per-cloud z reductions -> per-block partial slots ----------------
__global__ void __launch_bounds__(THREADS) k_pass1(
    const float4* __restrict__ coord4, const int4* __restrict__ seg4,
    const float*  __restrict__ coord,  const int*  __restrict__ segment,
    const int* __restrict__ offset, int n, int B, int gpt)
{
    __shared__ unsigned s_gmax[MAXB], s_pmin[MAXB], s_zmin[MAXB], s_zmax[MAXB];
    __shared__ int s_off[MAXB];

    int t = threadIdx.x;
    for (int j = t; j < B; j += THREADS) {
        s_gmax[j] = 0u;          s_pmin[j] = 0xFFFFFFFFu;
        s_zmin[j] = 0xFFFFFFFFu; s_zmax[j] = 0u;
        s_off[j]  = offset[j];
    }
    __syncthreads();

    int n4   = n >> 2;
    int lane = t & 31;
    int wbase = t & ~31;

    for (int k = 0; k < gpt; k++) {
        int gw0 = (blockIdx.x * gpt + k) * THREADS + wbase;  // warp's first group
        if (gw0 >= n4) break;                                // warp-uniform
        int g = gw0 + lane;
        bool act = (g < n4);

        // batch range covered by this warp's points
        int wp0 = gw0 << 2;
        int wpe = (min(gw0 + 32, n4) << 2) - 1;
        int b0 = 0; while (wp0 >= s_off[b0]) b0++;
        int b1 = b0; while (wpe >= s_off[b1]) b1++;

        float4 a, bb, c; int4 s;
        if (act) {
            a  = coord4[3 * g + 0];
            bb = coord4[3 * g + 1];
            c  = coord4[3 * g + 2];
            s  = seg4[g];
        }

        if (b0 == b1) {
            // uniform warp: shuffle-tree reduce, one shared atomic per value per warp
            unsigned lzm = 0xFFFFFFFFu, lzx = 0u, lg = 0u, lp = 0xFFFFFFFFu;
            if (act) {
                unsigned o0 = ordf(a.z), o1 = ordf(bb.y), o2 = ordf(c.x), o3 = ordf(c.w);
                lzm = min(min(o0, o1), min(o2, o3));
                lzx = max(max(o0, o1), max(o2, o3));
                lg  = max(max(s.x ? 0u : o0, s.y ? 0u : o1),
                          max(s.z ? 0u : o2, s.w ? 0u : o3));
                lp  = min(min(s.x ? o0 : 0xFFFFFFFFu, s.y ? o1 : 0xFFFFFFFFu),
                          min(s.z ? o2 : 0xFFFFFFFFu, s.w ? o3 : 0xFFFFFFFFu));
            }
            #pragma unroll
            for (int o = 16; o > 0; o >>= 1) {
                lzm = min(lzm, __shfl_xor_sync(0xFFFFFFFFu, lzm, o));
                lzx = max(lzx, __shfl_xor_sync(0xFFFFFFFFu, lzx, o));
                lg  = max(lg,  __shfl_xor_sync(0xFFFFFFFFu, lg,  o));
                lp  = min(lp,  __shfl_xor_sync(0xFFFFFFFFu, lp,  o));
            }
            if (lane == 0) {
                atomicMin(&s_zmin[b0], lzm);
                atomicMax(&s_zmax[b0], lzx);
                atomicMax(&s_gmax[b0], lg);     // identity 0u: no-op if warp had no ground
                atomicMin(&s_pmin[b0], lp);
            }
        } else if (act) {
            // rare straddle warp: per-point shared atomics
            int i0 = g << 2;
            float zz[4] = {a.z, bb.y, c.x, c.w};
            int   ss[4] = {s.x, s.y, s.z, s.w};
            int b = b0;
            #pragma unroll
            for (int q = 0; q < 4; q++) {
                int i = i0 + q;
                while (i >= s_off[b]) b++;
                unsigned o = ordf(zz[q]);
                atomicMin(&s_zmin[b], o);
                atomicMax(&s_zmax[b], o);
                if (ss[q]) atomicMin(&s_pmin[b], o);
                else       atomicMax(&s_gmax[b], o);
            }
        }
    }

    // tail points (n % 4), handled by block 0
    int tail0 = n4 << 2;
    if (blockIdx.x == 0 && t < (n - tail0)) {
        int i = tail0 + t;
        float z = coord[3 * i + 2];
        int  sv = segment[i];
        int b = 0; while (i >= s_off[b]) b++;
        unsigned o = ordf(z);
        atomicMin(&s_zmin[b], o);
        atomicMax(&s_zmax[b], o);
        if (sv) atomicMin(&s_pmin[b], o);
        else    atomicMax(&s_gmax[b], o);
    }

    __syncthreads();
    int row = blockIdx.x * B;
    for (int j = t; j < B; j += THREADS) {
        d_gmax[row + j] = s_gmax[j];
        d_pmin[row + j] = s_pmin[j];
        d_zmin[row + j] = s_zmin[j];
        d_zmax[row + j] = s_zmax[j];
    }
}

// ---------------- kernel 2: combine partials -> mu per cloud; reset counter ----------------
__global__ void __launch_bounds__(THREADS) k_mid(int B, int nblk)
{
    int b = blockIdx.x;      // grid = B
    int t = threadIdx.x;
    unsigned gm = 0u, pm = 0xFFFFFFFFu, zm = 0xFFFFFFFFu, zx = 0u;
    for (int r = t; r < nblk; r += THREADS) {
        int idx = r * B + b;
        gm = max(gm, d_gmax[idx]);
        pm = min(pm, d_pmin[idx]);
        zm = min(zm, d_zmin[idx]);
        zx = max(zx, d_zmax[idx]);
    }
    __shared__ unsigned sg[THREADS], sp[THREADS], sm[THREADS], sx[THREADS];
    sg[t] = gm; sp[t] = pm; sm[t] = zm; sx[t] = zx;
    __syncthreads();
    for (int s = THREADS / 2; s > 0; s >>= 1) {
        if (t < s) {
            sg[t] = max(sg[t], sg[t + s]);
            sp[t] = min(sp[t], sp[t + s]);
            sm[t] = min(sm[t], sm[t + s]);
            sx[t] = max(sx[t], sx[t + s]);
        }
        __syncthreads();
    }
    if (t == 0) {
        float g = (sg[0] != 0u)          ? deordf(sg[0]) : deordf(sm[0]);
        float p = (sp[0] != 0xFFFFFFFFu) ? deordf(sp[0]) : deordf(sx[0]);
        d_mu[b] = g + (p - g) * 0.5f;
        if (b == 0) d_count = 0u;
    }
}

// ---------------- kernel 3: focal-CE * gaussian weight, reduce + finalize ----------------
__device__ __forceinline__ float pointTerm(float p0, float p1, int s, float z, float mu)
{
    float tgt = s ? p1 : p0;
    float oth = s ? p0 : p1;
    float v   = oth - tgt;
    float e   = __expf(-fabsf(v));
    float inv = frcp(1.0f + e);
    float sig = (v >= 0.0f ? 1.0f : e) * inv;       // 1 - p_t
    float sp  = fmaxf(v, 0.0f) + __logf(1.0f + e);  // -log p_t
    float d   = z - mu;
    float dd  = d * d;
    float cf  = (d <= 0.0f) ? -50.0f : -3.125f;     // 1/(2*0.1^2), 1/(2*0.4^2)
    float w   = __expf(cf * dd);
    if (d > 0.8f) w = 0.1f;                         // clamp past 2*SIGMA_R
    return sp * sig * sig * w;
}

__global__ void __launch_bounds__(THREADS) k_loss(
    const float4* __restrict__ pred4, const float* __restrict__ pred,
    const float4* __restrict__ coord4, const float* __restrict__ coord,
    const int4* __restrict__ seg4, const int* __restrict__ segment,
    const int* __restrict__ offset, int n, int B, int gpt, float* __restrict__ out)
{
    __shared__ int    s_off[MAXB];
    __shared__ float  s_mu[MAXB];
    __shared__ float  s_w[THREADS / 32];
    __shared__ bool   s_last;
    __shared__ double s_d[THREADS];

    int t = threadIdx.x;
    for (int j = t; j < B; j += THREADS) {
        s_off[j] = offset[j];
        s_mu[j]  = d_mu[j];
    }
    __syncthreads();

    int n4 = n >> 2;
    float acc = 0.0f;

    int gb0 = blockIdx.x * gpt * THREADS;
    int gbe = min(gb0 + gpt * THREADS, n4);
    if (gb0 < n4) {
        int p0 = gb0 << 2;
        int pe = (gbe << 2) - 1;
        int b0 = 0; while (p0 >= s_off[b0]) b0++;
        int b1 = b0; while (pe >= s_off[b1]) b1++;
        bool uni = (b0 == b1);
        float muu = s_mu[b0];
        int curb = b0;

        for (int k = 0; k < gpt; k++) {
            int g = gb0 + k * THREADS + t;
            if (g >= n4) break;
            float4 pa = pred4[2 * g + 0];
            float4 pb = pred4[2 * g + 1];
            float4 a  = coord4[3 * g + 0];
            float4 bb = coord4[3 * g + 1];
            float4 c  = coord4[3 * g + 2];
            int4   s  = seg4[g];

            float mu0 = muu, mu1 = muu, mu2 = muu, mu3 = muu;
            if (!uni) {
                int i0 = g << 2;
                while (i0 >= s_off[curb]) curb++;
                int q1 = curb; while (i0 + 1 >= s_off[q1]) q1++;
                int q2 = q1;   while (i0 + 2 >= s_off[q2]) q2++;
                int q3 = q2;   while (i0 + 3 >= s_off[q3]) q3++;
                mu0 = s_mu[curb]; mu1 = s_mu[q1]; mu2 = s_mu[q2]; mu3 = s_mu[q3];
            }
            acc += pointTerm(pa.x, pa.y, s.x, a.z,  mu0);
            acc += pointTerm(pa.z, pa.w, s.y, bb.y, mu1);
            acc += pointTerm(pb.x, pb.y, s.z, c.x,  mu2);
            acc += pointTerm(pb.z, pb.w, s.w, c.w,  mu3);
        }
    }

    // tail points (block 0)
    int tail0 = n4 << 2;
    if (blockIdx.x == 0 && t < (n - tail0)) {
        int i = tail0 + t;
        int b = 0; while (i >= s_off[b]) b++;
        acc += pointTerm(pred[2 * i], pred[2 * i + 1], segment[i],
                         coord[3 * i + 2], s_mu[b]);
    }

    // block reduce: warp shuffle -> shared -> warp 0
    #pragma unroll
    for (int o = 16; o > 0; o >>= 1) acc += __shfl_xor_sync(0xFFFFFFFFu, acc, o);
    int warp = t >> 5, lane = t & 31;
    if (lane == 0) s_w[warp] = acc;
    __syncthreads();
    if (t == 0) {
        float tot = 0.0f;
        #pragma unroll
        for (int w = 0; w < THREADS / 32; w++) tot += s_w[w];
        d_part[blockIdx.x] = tot;
        __threadfence();
        unsigned old = atomicAdd(&d_count, 1u);
        s_last = (old == gridDim.x - 1);
    }
    __syncthreads();

    // last-arriving block: deterministic double-precision final sum + mean
    if (s_last) {
        double da = 0.0;
        for (int i = t; i < (int)gridDim.x; i += THREADS) da += (double)d_part[i];
        s_d[t] = da;
        __syncthreads();
        for (int s = THREADS / 2; s > 0; s >>= 1) {
            if (t < s) s_d[t] += s_d[t + s];
            __syncthreads();
        }
        if (t == 0) out[0] = (float)(s_d[0] / (double)n);
    }
}

// ---------------- launch ----------------
extern "C" void kernel_launch(void* const* d_in, const int* in_sizes, int n_in,
                              void* d_out, int out_size)
{
    const float* pred    = (const float*)d_in[0];
    const float* coord   = (const float*)d_in[1];
    const int*   segment = (const int*)d_in[2];
    const int*   offset  = (const int*)d_in[3];
    int n = in_sizes[2];
    int B = in_sizes[3];
    if (B > MAXB) B = MAXB;
    if (B < 1) B = 1;

    int n4 = n >> 2;
    int gpt = 1;
    long long need = ((long long)n4 + THREADS - 1) / THREADS;
    if (need > MAXBLK) gpt = (int)((need + MAXBLK - 1) / MAXBLK);
    int nblk = (int)((n4 + (long long)gpt * THREADS - 1) / ((long long)gpt * THREADS));
    if (nblk < 1) nblk = 1;

    k_pass1<<<nblk, THREADS>>>((const float4*)coord, (const int4*)segment,
                               coord, segment, offset, n, B, gpt);
    k_mid<<<B, THREADS>>>(B, nblk);
    k_loss<<<nblk, THREADS>>>((const float4*)pred, pred,
                              (const float4*)coord, coord,
                              (const int4*)segment, segment,
                              offset, n, B, gpt, (float*)d_out);
}

// round 4
// speedup vs baseline: 1.3524x; 1.1033x over previous
#include <cuda_runtime.h>
#include <cuda_bf16.h>

#define THREADS 256
#define NBLK    1184          // 148 SMs * 8 blocks
#define NWARP   (THREADS / 32)
#define MAXB    64

// ---------------- device scratch (no allocations allowed) ----------------
__device__ unsigned d_gmax[MAXB * NBLK];   // column-major: [batch][block]
__device__ unsigned d_pmin[MAXB * NBLK];
__device__ unsigned d_zmin[MAXB * NBLK];
__device__ unsigned d_zmax[MAXB * NBLK];
__device__ float    d_part[NBLK];
__device__ float    d_mu[MAXB];
__device__ unsigned d_c1;                  // zero-init; each kernel resets its own
__device__ unsigned d_c2;

// order-preserving float <-> uint
__device__ __forceinline__ unsigned ordf(float f) {
    unsigned u = __float_as_uint(f);
    return (u & 0x80000000u) ? ~u : (u | 0x80000000u);
}
__device__ __forceinline__ float deordf(unsigned o) {
    unsigned u = (o & 0x80000000u) ? (o & 0x7FFFFFFFu) : ~o;
    return __uint_as_float(u);
}
__device__ __forceinline__ float frcp(float x) {
    float r; asm("rcp.approx.f32 %0, %1;" : "=f"(r) : "f"(x)); return r;
}

// ================= kernel 1: per-cloud z reductions + mu (fused combine) =================
__global__ void __launch_bounds__(THREADS) k_pass1(
    const float4* __restrict__ coord4, const int4* __restrict__ seg4,
    const float*  __restrict__ coord,  const int*  __restrict__ segment,
    const int* __restrict__ offset, int n, int B, int gpb)
{
    __shared__ unsigned s_gmax[MAXB], s_pmin[MAXB], s_zmin[MAXB], s_zmax[MAXB];
    __shared__ int s_off[MAXB];
    __shared__ unsigned s_rg[NWARP], s_rp[NWARP], s_rm[NWARP], s_rx[NWARP];
    __shared__ bool s_last;

    int t = threadIdx.x;
    int bid = blockIdx.x;
    int lane = t & 31, warp = t >> 5;

    for (int j = t; j < B; j += THREADS) {
        s_gmax[j] = 0u;  s_pmin[j] = ~0u;
        s_zmin[j] = ~0u; s_zmax[j] = 0u;
        s_off[j]  = offset[j];
    }
    __syncthreads();

    int n4 = n >> 2;
    int g0 = bid * gpb;
    int g1 = min(g0 + gpb, n4);
    bool isLast = (bid == (int)gridDim.x - 1);
    int tail0 = n4 << 2;
    bool hasWork = (g0 < g1) || (isLast && tail0 < n);

    if (hasWork) {
        int p0 = min(g0 << 2, n - 1);
        int pe = isLast ? (n - 1) : ((g1 << 2) - 1);
        int b0 = 0; while (p0 >= s_off[b0]) b0++;
        int b1 = b0; while (pe >= s_off[b1]) b1++;

        if (b0 == b1) {
            // ---- fast path: whole block in one batch; pure streaming ----
            unsigned lzm = ~0u, lzx = 0u, lg = 0u, lp = ~0u;
            for (int g = g0 + t; g < g1; g += THREADS) {
                float4 a  = coord4[3 * g + 0];
                float4 bb = coord4[3 * g + 1];
                float4 c  = coord4[3 * g + 2];
                int4   s  = seg4[g];
                unsigned o0 = ordf(a.z), o1 = ordf(bb.y), o2 = ordf(c.x), o3 = ordf(c.w);
                lzm = min(lzm, min(min(o0, o1), min(o2, o3)));
                lzx = max(lzx, max(max(o0, o1), max(o2, o3)));
                lg  = max(lg, max(max(s.x ? 0u : o0, s.y ? 0u : o1),
                                  max(s.z ? 0u : o2, s.w ? 0u : o3)));
                lp  = min(lp, min(min(s.x ? o0 : ~0u, s.y ? o1 : ~0u),
                                  min(s.z ? o2 : ~0u, s.w ? o3 : ~0u)));
            }
            if (isLast) {
                for (int i = tail0 + t; i < n; i += THREADS) {
                    unsigned o = ordf(coord[3 * i + 2]);
                    if (segment[i]) lp = min(lp, o); else lg = max(lg, o);
                    lzm = min(lzm, o); lzx = max(lzx, o);
                }
            }
            #pragma unroll
            for (int o = 16; o > 0; o >>= 1) {
                lzm = min(lzm, __shfl_xor_sync(~0u, lzm, o));
                lzx = max(lzx, __shfl_xor_sync(~0u, lzx, o));
                lg  = max(lg,  __shfl_xor_sync(~0u, lg,  o));
                lp  = min(lp,  __shfl_xor_sync(~0u, lp,  o));
            }
            if (lane == 0) {
                atomicMin(&s_zmin[b0], lzm);
                atomicMax(&s_zmax[b0], lzx);
                atomicMax(&s_gmax[b0], lg);
                atomicMin(&s_pmin[b0], lp);
            }
        } else {
            // ---- slow path (<=7 straddle blocks): per-warp uniformity ----
            int wbase = t & ~31;
            for (int gw = g0 + wbase; gw < g1; gw += THREADS) {
                int g = gw + lane;
                bool act = (g < g1);
                int wp0 = gw << 2;
                int wpe = (min(gw + 32, g1) << 2) - 1;
                int c0 = 0; while (wp0 >= s_off[c0]) c0++;
                int c1 = c0; while (wpe >= s_off[c1]) c1++;

                float4 a, bb, c; int4 s;
                if (act) {
                    a = coord4[3 * g + 0]; bb = coord4[3 * g + 1];
                    c = coord4[3 * g + 2]; s = seg4[g];
                }
                if (c0 == c1) {
                    unsigned lzm = ~0u, lzx = 0u, lg = 0u, lp = ~0u;
                    if (act) {
                        unsigned o0 = ordf(a.z), o1 = ordf(bb.y), o2 = ordf(c.x), o3 = ordf(c.w);
                        lzm = min(min(o0, o1), min(o2, o3));
                        lzx = max(max(o0, o1), max(o2, o3));
                        lg  = max(max(s.x ? 0u : o0, s.y ? 0u : o1),
                                  max(s.z ? 0u : o2, s.w ? 0u : o3));
                        lp  = min(min(s.x ? o0 : ~0u, s.y ? o1 : ~0u),
                                  min(s.z ? o2 : ~0u, s.w ? o3 : ~0u));
                    }
                    #pragma unroll
                    for (int o = 16; o > 0; o >>= 1) {
                        lzm = min(lzm, __shfl_xor_sync(~0u, lzm, o));
                        lzx = max(lzx, __shfl_xor_sync(~0u, lzx, o));
                        lg  = max(lg,  __shfl_xor_sync(~0u, lg,  o));
                        lp  = min(lp,  __shfl_xor_sync(~0u, lp,  o));
                    }
                    if (lane == 0) {
                        atomicMin(&s_zmin[c0], lzm);
                        atomicMax(&s_zmax[c0], lzx);
                        atomicMax(&s_gmax[c0], lg);
                        atomicMin(&s_pmin[c0], lp);
                    }
                } else if (act) {
                    int i0 = g << 2;
                    float zz[4] = {a.z, bb.y, c.x, c.w};
                    int   ss[4] = {s.x, s.y, s.z, s.w};
                    int b = c0;
                    #pragma unroll
                    for (int q = 0; q < 4; q++) {
                        int i = i0 + q;
                        while (i >= s_off[b]) b++;
                        unsigned o = ordf(zz[q]);
                        atomicMin(&s_zmin[b], o);
                        atomicMax(&s_zmax[b], o);
                        if (ss[q]) atomicMin(&s_pmin[b], o);
                        else       atomicMax(&s_gmax[b], o);
                    }
                }
            }
            if (isLast) {
                for (int i = tail0 + t; i < n; i += THREADS) {
                    int b = 0; while (i >= s_off[b]) b++;
                    unsigned o = ordf(coord[3 * i + 2]);
                    atomicMin(&s_zmin[b], o);
                    atomicMax(&s_zmax[b], o);
                    if (segment[i]) atomicMin(&s_pmin[b], o);
                    else            atomicMax(&s_gmax[b], o);
                }
            }
        }
    }

    __syncthreads();
    for (int j = t; j < B; j += THREADS) {
        d_gmax[j * NBLK + bid] = s_gmax[j];
        d_pmin[j * NBLK + bid] = s_pmin[j];
        d_zmin[j * NBLK + bid] = s_zmin[j];
        d_zmax[j * NBLK + bid] = s_zmax[j];
    }
    __threadfence();
    if (t == 0) s_last = (atomicAdd(&d_c1, 1u) == gridDim.x - 1);
    __syncthreads();

    // last-arriving block combines partials -> mu, resets counter
    if (s_last) {
        for (int j = 0; j < B; j++) {
            unsigned gm = 0u, pm = ~0u, zm = ~0u, zx = 0u;
            for (int r = t; r < (int)gridDim.x; r += THREADS) {
                gm = max(gm, d_gmax[j * NBLK + r]);
                pm = min(pm, d_pmin[j * NBLK + r]);
                zm = min(zm, d_zmin[j * NBLK + r]);
                zx = max(zx, d_zmax[j * NBLK + r]);
            }
            #pragma unroll
            for (int o = 16; o > 0; o >>= 1) {
                gm = max(gm, __shfl_xor_sync(~0u, gm, o));
                pm = min(pm, __shfl_xor_sync(~0u, pm, o));
                zm = min(zm, __shfl_xor_sync(~0u, zm, o));
                zx = max(zx, __shfl_xor_sync(~0u, zx, o));
            }
            if (lane == 0) { s_rg[warp] = gm; s_rp[warp] = pm; s_rm[warp] = zm; s_rx[warp] = zx; }
            __syncthreads();
            if (t == 0) {
                #pragma unroll
                for (int w = 1; w < NWARP; w++) {
                    gm = max(s_rg[0], gm); gm = max(gm, s_rg[w]);
                    pm = min(pm, s_rp[w]); zm = min(zm, s_rm[w]); zx = max(zx, s_rx[w]);
                }
                gm = s_rg[0]; pm = s_rp[0]; zm = s_rm[0]; zx = s_rx[0];
                #pragma unroll
                for (int w = 1; w < NWARP; w++) {
                    gm = max(gm, s_rg[w]); pm = min(pm, s_rp[w]);
                    zm = min(zm, s_rm[w]); zx = max(zx, s_rx[w]);
                }
                float g = (gm != 0u)  ? deordf(gm) : deordf(zm);
                float p = (pm != ~0u) ? deordf(pm) : deordf(zx);
                d_mu[j] = g + (p - g) * 0.5f;
            }
            __syncthreads();
        }
        if (t == 0) d_c1 = 0u;
    }
}

// ================= kernel 2: focal-CE * gaussian, reduce + finalize =================
__device__ __forceinline__ float pointTerm(float p0, float p1, int s, float z, float mu)
{
    float tgt = s ? p1 : p0;
    float oth = s ? p0 : p1;
    float v   = oth - tgt;
    float e   = __expf(-fabsf(v));
    float inv = frcp(1.0f + e);
    float sig = (v >= 0.0f ? 1.0f : e) * inv;       // 1 - p_t
    float sp  = fmaxf(v, 0.0f) + __logf(1.0f + e);  // -log p_t
    float d   = z - mu;
    float dd  = d * d;
    float cf  = (d <= 0.0f) ? -50.0f : -3.125f;     // 1/(2*0.1^2), 1/(2*0.4^2)
    float w   = __expf(cf * dd);
    if (d > 0.8f) w = 0.1f;                         // clamp past 2*SIGMA_R
    return sp * sig * sig * w;
}

__global__ void __launch_bounds__(THREADS) k_loss(
    const float4* __restrict__ pred4, const float* __restrict__ pred,
    const float4* __restrict__ coord4, const float* __restrict__ coord,
    const int4* __restrict__ seg4, const int* __restrict__ segment,
    const int* __restrict__ offset, int n, int B, int gpb, float* __restrict__ out)
{
    __shared__ int    s_off[MAXB];
    __shared__ float  s_mu[MAXB];
    __shared__ float  s_w[NWARP];
    __shared__ bool   s_last;
    __shared__ double s_d[THREADS];

    int t = threadIdx.x;
    int bid = blockIdx.x;
    for (int j = t; j < B; j += THREADS) {
        s_off[j] = offset[j];
        s_mu[j]  = d_mu[j];
    }
    __syncthreads();

    int n4 = n >> 2;
    int g0 = bid * gpb;
    int g1 = min(g0 + gpb, n4);
    bool isLast = (bid == (int)gridDim.x - 1);
    int tail0 = n4 << 2;

    float acc = 0.0f;

    if (g0 < g1) {
        int p0 = g0 << 2;
        int pe = isLast ? (n - 1) : ((g1 << 2) - 1);
        int b0 = 0; while (p0 >= s_off[b0]) b0++;
        int b1 = b0; while (pe >= s_off[b1]) b1++;
        bool uni = (b0 == b1);
        float muu = s_mu[b0];
        int curb = b0;

        for (int g = g0 + t; g < g1; g += THREADS) {
            float4 pa = pred4[2 * g + 0];
            float4 pb = pred4[2 * g + 1];
            float4 a  = coord4[3 * g + 0];
            float4 bb = coord4[3 * g + 1];
            float4 c  = coord4[3 * g + 2];
            int4   s  = seg4[g];

            float mu0 = muu, mu1 = muu, mu2 = muu, mu3 = muu;
            if (!uni) {
                int i0 = g << 2;
                while (i0 >= s_off[curb]) curb++;
                int q1 = curb; while (i0 + 1 >= s_off[q1]) q1++;
                int q2 = q1;   while (i0 + 2 >= s_off[q2]) q2++;
                int q3 = q2;   while (i0 + 3 >= s_off[q3]) q3++;
                mu0 = s_mu[curb]; mu1 = s_mu[q1]; mu2 = s_mu[q2]; mu3 = s_mu[q3];
            }
            acc += pointTerm(pa.x, pa.y, s.x, a.z,  mu0);
            acc += pointTerm(pa.z, pa.w, s.y, bb.y, mu1);
            acc += pointTerm(pb.x, pb.y, s.z, c.x,  mu2);
            acc += pointTerm(pb.z, pb.w, s.w, c.w,  mu3);
        }
    }

    if (isLast && t < (n - tail0)) {
        int i = tail0 + t;
        int b = 0; while (i >= s_off[b]) b++;
        acc += pointTerm(pred[2 * i], pred[2 * i + 1], segment[i],
                         coord[3 * i + 2], s_mu[b]);
    }

    // block reduce
    #pragma unroll
    for (int o = 16; o > 0; o >>= 1) acc += __shfl_xor_sync(~0u, acc, o);
    int warp = t >> 5, lane = t & 31;
    if (lane == 0) s_w[warp] = acc;
    __syncthreads();
    if (t == 0) {
        float tot = 0.0f;
        #pragma unroll
        for (int w = 0; w < NWARP; w++) tot += s_w[w];
        d_part[bid] = tot;
        __threadfence();
        s_last = (atomicAdd(&d_c2, 1u) == gridDim.x - 1);
    }
    __syncthreads();

    if (s_last) {
        double da = 0.0;
        for (int i = t; i < (int)gridDim.x; i += THREADS) da += (double)d_part[i];
        s_d[t] = da;
        __syncthreads();
        for (int s = THREADS / 2; s > 0; s >>= 1) {
            if (t < s) s_d[t] += s_d[t + s];
            __syncthreads();
        }
        if (t == 0) { out[0] = (float)(s_d[0] / (double)n); d_c2 = 0u; }
    }
}

// ---------------- launch ----------------
extern "C" void kernel_launch(void* const* d_in, const int* in_sizes, int n_in,
                              void* d_out, int out_size)
{
    const float* pred    = (const float*)d_in[0];
    const float* coord   = (const float*)d_in[1];
    const int*   segment = (const int*)d_in[2];
    const int*   offset  = (const int*)d_in[3];
    int n = in_sizes[2];
    int B = in_sizes[3];
    if (B > MAXB) B = MAXB;
    if (B < 1) B = 1;

    int n4 = n >> 2;
    int gpb = (n4 + NBLK - 1) / NBLK;
    if (gpb < 1) gpb = 1;

    k_pass1<<<NBLK, THREADS>>>((const float4*)coord, (const int4*)segment,
                               coord, segment, offset, n, B, gpb);
    k_loss<<<NBLK, THREADS>>>((const float4*)pred, pred,
                              (const float4*)coord, coord,
                              (const int4*)segment, segment,
                              offset, n, B, gpb, (float*)d_out);
}